// round 1
// baseline (speedup 1.0000x reference)
#include <cuda_runtime.h>
#include <math.h>

#define BATCH 2
#define NPT   1000
#define KNN   8
#define NPAIR 499500   // N*(N-1)/2

// ---------------- static scratch (no allocation allowed) ----------------
__device__ float g_x1[BATCH * NPT * 32];
__device__ float g_x2[BATCH * NPT * 128];
__device__ float g_x3[BATCH * NPT * 512];
__device__ int   g_idx[BATCH * NPT * KNN];
__device__ float g_A [BATCH * NPT * 256];
__device__ float g_Bv[BATCH * NPT * 256];
__device__ float g_sf[BATCH * NPT * 128];
__device__ float g_hi[BATCH * NPT * 128];
__device__ float g_hj[BATCH * NPT * 128];
__device__ float g_hg[BATCH * 128];

// ---------------- kNN: per (b,i) block, top-8 smallest d2 ----------------
// d2 = |xi|^2 + |xj|^2 - 2<xi,xj>, ties broken by smaller index (matches lax.top_k)
__global__ void knn_kernel(const float* __restrict__ x, int C, int* __restrict__ idxout) {
    int node = blockIdx.x;            // b*NPT + i
    int b = node / NPT;
    int tid = threadIdx.x;            // 128 threads

    __shared__ float xi[128];
    __shared__ float shd[128 * 8];
    __shared__ int   shi[128 * 8];

    for (int c = tid; c < C; c += 128) xi[c] = x[node * C + c];
    __syncthreads();

    float sqi = 0.f;
    for (int c = 0; c < C; c++) sqi = fmaf(xi[c], xi[c], sqi);

    float bd[8]; int bi[8];
#pragma unroll
    for (int s = 0; s < 8; s++) { bd[s] = 3.4e38f; bi[s] = 0x7fffffff; }

    const float* xb = x + (size_t)b * NPT * C;
    for (int j = tid; j < NPT; j += 128) {
        const float* xj = xb + j * C;
        float dot = 0.f, sqj = 0.f;
        for (int c = 0; c < C; c++) {
            float v = xj[c];
            dot = fmaf(xi[c], v, dot);
            sqj = fmaf(v, v, sqj);
        }
        float d2 = (sqi + sqj) - 2.f * dot;
        if (d2 < bd[7] || (d2 == bd[7] && j < bi[7])) {
            int p = 7;
            while (p > 0 && (d2 < bd[p-1] || (d2 == bd[p-1] && j < bi[p-1]))) {
                bd[p] = bd[p-1]; bi[p] = bi[p-1]; p--;
            }
            bd[p] = d2; bi[p] = j;
        }
    }
#pragma unroll
    for (int s = 0; s < 8; s++) { shd[tid*8+s] = bd[s]; shi[tid*8+s] = bi[s]; }
    __syncthreads();

    // pairwise sorted-list merge reduction
    for (int str = 64; str > 0; str >>= 1) {
        if (tid < str) {
            float* A1 = &shd[tid*8];         int* I1 = &shi[tid*8];
            float* A2 = &shd[(tid+str)*8];   int* I2 = &shi[(tid+str)*8];
            float od[8]; int oi[8];
            int a = 0, c2 = 0;
#pragma unroll
            for (int t = 0; t < 8; t++) {
                bool takeA = (A1[a] < A2[c2]) || (A1[a] == A2[c2] && I1[a] <= I2[c2]);
                if (takeA) { od[t] = A1[a]; oi[t] = I1[a]; a++; }
                else       { od[t] = A2[c2]; oi[t] = I2[c2]; c2++; }
            }
#pragma unroll
            for (int t = 0; t < 8; t++) { A1[t] = od[t]; I1[t] = oi[t]; }
        }
        __syncthreads();
    }
    if (tid < 8) idxout[node * 8 + tid] = shi[tid];
}

// ---------------- per-node A = x@W1_top, Bv = x@W1_bot ----------------
__global__ void ab_kernel(const float* __restrict__ x, const float* __restrict__ w1,
                          int C, int H, float* __restrict__ A, float* __restrict__ Bv) {
    int node = blockIdx.x;
    int tid = threadIdx.x;
    __shared__ float xs[128];
    for (int c = tid; c < C; c += blockDim.x) xs[c] = x[node * C + c];
    __syncthreads();
    for (int h = tid; h < H; h += blockDim.x) {
        float a = 0.f, bb = 0.f;
        for (int c = 0; c < C; c++) {
            float v = xs[c];
            a  = fmaf(v, w1[c * H + h],        a);
            bb = fmaf(v, w1[(C + c) * H + h],  bb);
        }
        A [node * H + h] = a;
        Bv[node * H + h] = bb;
    }
}

// ---------------- edge MLP2 + max aggregation ----------------
// h_k = relu(A_i - Bv_i + Bv_j + b1); out = max_k (h_k @ w2 + b2)
template<int H, int COUT, int T, int VC>
__global__ void edge_kernel(const float* __restrict__ A, const float* __restrict__ Bv,
                            const int* __restrict__ idx, const float* __restrict__ b1,
                            const float* __restrict__ w2, const float* __restrict__ b2,
                            float* __restrict__ xout) {
    static_assert(T * VC == COUT, "layout");
    int node = blockIdx.x;
    int tid = threadIdx.x;
    __shared__ float aic[H];
    __shared__ float hsh[H];

    for (int hh = tid; hh < H; hh += T)
        aic[hh] = A[node * H + hh] - Bv[node * H + hh] + b1[hh];

    float m[VC];
#pragma unroll
    for (int r = 0; r < VC; r++) m[r] = -3.4e38f;

    int bbase = (node / NPT) * NPT;
    __syncthreads();

    for (int kk = 0; kk < KNN; kk++) {
        int j = idx[node * KNN + kk];
        const float* bvj = Bv + (size_t)(bbase + j) * H;
        for (int hh = tid; hh < H; hh += T)
            hsh[hh] = fmaxf(aic[hh] + bvj[hh], 0.f);
        __syncthreads();

        float acc[VC];
#pragma unroll
        for (int r = 0; r < VC; r++) acc[r] = b2[tid * VC + r];

        if (VC == 4) {
#pragma unroll 4
            for (int hh = 0; hh < H; hh++) {
                float hv = hsh[hh];
                float4 w = *reinterpret_cast<const float4*>(w2 + (size_t)hh * COUT + tid * 4);
                acc[0] = fmaf(hv, w.x, acc[0]);
                acc[1] = fmaf(hv, w.y, acc[1]);
                acc[2] = fmaf(hv, w.z, acc[2]);
                acc[3] = fmaf(hv, w.w, acc[3]);
            }
        } else {
#pragma unroll 4
            for (int hh = 0; hh < H; hh++) {
                float hv = hsh[hh];
                const float* wrow = w2 + (size_t)hh * COUT + tid * VC;
#pragma unroll
                for (int r = 0; r < VC; r++) acc[r] = fmaf(hv, wrow[r], acc[r]);
            }
        }
#pragma unroll
        for (int r = 0; r < VC; r++) m[r] = fmaxf(m[r], acc[r]);
        __syncthreads();
    }
#pragma unroll
    for (int r = 0; r < VC; r++) xout[(size_t)node * COUT + tid * VC + r] = m[r];
}

// ---------------- sf = MLP(concat(x1,x2,x3)); also hi/hj projections ----------------
__global__ void sf_kernel(const float* __restrict__ x1, const float* __restrict__ x2,
                          const float* __restrict__ x3,
                          const float* __restrict__ w1, const float* __restrict__ b1,
                          const float* __restrict__ w2, const float* __restrict__ b2,
                          const float* __restrict__ ecw1,
                          float* __restrict__ sf, float* __restrict__ hi, float* __restrict__ hj) {
    int node = blockIdx.x;
    int tid = threadIdx.x;   // 256
    __shared__ float xin[672];
    __shared__ float hsh[256];
    __shared__ float sfs[128];

    for (int c = tid; c < 32;  c += 256) xin[c]       = x1[node * 32 + c];
    for (int c = tid; c < 128; c += 256) xin[32 + c]  = x2[node * 128 + c];
    for (int c = tid; c < 512; c += 256) xin[160 + c] = x3[(size_t)node * 512 + c];
    __syncthreads();

    {
        float acc = b1[tid];
#pragma unroll 4
        for (int d = 0; d < 672; d++) acc = fmaf(xin[d], w1[d * 256 + tid], acc);
        hsh[tid] = fmaxf(acc, 0.f);
    }
    __syncthreads();

    if (tid < 128) {
        float acc = b2[tid];
#pragma unroll 8
        for (int d = 0; d < 256; d++) acc = fmaf(hsh[d], w2[d * 128 + tid], acc);
        sfs[tid] = acc;
        sf[node * 128 + tid] = acc;
    }
    __syncthreads();

    if (tid < 128) {
        float a1 = 0.f, a2 = 0.f;
#pragma unroll 8
        for (int d = 0; d < 128; d++) {
            float s = sfs[d];
            a1 = fmaf(s, ecw1[d * 128 + tid],         a1);
            a2 = fmaf(s, ecw1[(128 + d) * 128 + tid], a2);
        }
        hi[node * 128 + tid] = a1;
        hj[node * 128 + tid] = a2;
    }
}

// ---------------- global max pool + hg = g@ec_w1[256:] + ec_b1 ----------------
__global__ void gmax_kernel(const float* __restrict__ sf, const float* __restrict__ ecw1,
                            const float* __restrict__ ecb1, float* __restrict__ hg) {
    int b = blockIdx.x;
    int tid = threadIdx.x;  // 128
    __shared__ float gsh[128];
    float m = -3.4e38f;
    for (int n = 0; n < NPT; n++)
        m = fmaxf(m, sf[(size_t)(b * NPT + n) * 128 + tid]);
    gsh[tid] = m;
    __syncthreads();
    float acc = ecb1[tid];
#pragma unroll 8
    for (int d = 0; d < 128; d++)
        acc = fmaf(gsh[d], ecw1[(256 + d) * 128 + tid], acc);
    hg[b * 128 + tid] = acc;
}

// ---------------- all-pairs classifier: 32x32 tiles over triu pairs ----------------
__global__ void pairs_kernel(const float* __restrict__ hi, const float* __restrict__ hj,
                             const float* __restrict__ hg, const float* __restrict__ ecw2,
                             const float* __restrict__ ecb2, float* __restrict__ out,
                             int writeBoth) {
    int it = blockIdx.x, jt = blockIdx.y, b = blockIdx.z;
    if (jt < it) return;

    __shared__ float shi[32 * 128];
    __shared__ float shj[32 * 128];
    __shared__ float w2s[128];

    int tid = threadIdx.x;  // 256
    if (tid < 128) w2s[tid] = ecw2[tid];

    for (int t = tid; t < 32 * 128; t += 256) {
        int r = t >> 7, c = t & 127;
        int i = it * 32 + r;
        shi[t] = (i < NPT) ? (hi[(size_t)(b * NPT + i) * 128 + c] + hg[b * 128 + c]) : 0.f;
        int j = jt * 32 + r;
        shj[t] = (j < NPT) ? hj[(size_t)(b * NPT + j) * 128 + c] : 0.f;
    }
    __syncthreads();

    int warp = tid >> 5, lane = tid & 31;
    float w0 = w2s[lane * 4 + 0];
    float w1 = w2s[lane * 4 + 1];
    float w2v = w2s[lane * 4 + 2];
    float w3 = w2s[lane * 4 + 3];
    float bias = ecb2[0];

    const float4* shi4 = reinterpret_cast<const float4*>(shi);
    const float4* shj4 = reinterpret_cast<const float4*>(shj);

    for (int lp = warp; lp < 1024; lp += 8) {
        int ri = lp >> 5, rj = lp & 31;
        int i = it * 32 + ri, j = jt * 32 + rj;
        if (i >= NPT || j >= NPT || j <= i) continue;

        float4 a = shi4[ri * 32 + lane];
        float4 bb = shj4[rj * 32 + lane];
        float acc = fmaxf(a.x + bb.x, 0.f) * w0
                  + fmaxf(a.y + bb.y, 0.f) * w1
                  + fmaxf(a.z + bb.z, 0.f) * w2v
                  + fmaxf(a.w + bb.w, 0.f) * w3;
#pragma unroll
        for (int s = 16; s > 0; s >>= 1) acc += __shfl_down_sync(0xffffffffu, acc, s);

        if (lane == 0) {
            float v = acc + bias;
            int p = i * (NPT - 1) - (i * (i - 1)) / 2 + (j - i - 1);
            float prob = 1.f / (1.f + expf(-v));
            size_t base = (size_t)b * NPAIR + p;
            out[base] = prob;
            if (writeBoth) out[(size_t)BATCH * NPAIR + base] = v;
        }
    }
}

// ---------------- host launch ----------------
extern "C" void kernel_launch(void* const* d_in, const int* in_sizes, int n_in,
                              void* d_out, int out_size) {
    const float* pos   = (const float*)d_in[0];
    const float* c1_w1 = (const float*)d_in[1];
    const float* c1_b1 = (const float*)d_in[2];
    const float* c1_w2 = (const float*)d_in[3];
    const float* c1_b2 = (const float*)d_in[4];
    const float* c2_w1 = (const float*)d_in[5];
    const float* c2_b1 = (const float*)d_in[6];
    const float* c2_w2 = (const float*)d_in[7];
    const float* c2_b2 = (const float*)d_in[8];
    const float* c3_w1 = (const float*)d_in[9];
    const float* c3_b1 = (const float*)d_in[10];
    const float* c3_w2 = (const float*)d_in[11];
    const float* c3_b2 = (const float*)d_in[12];
    const float* sm_w1 = (const float*)d_in[13];
    const float* sm_b1 = (const float*)d_in[14];
    const float* sm_w2 = (const float*)d_in[15];
    const float* sm_b2 = (const float*)d_in[16];
    const float* ec_w1 = (const float*)d_in[17];
    const float* ec_b1 = (const float*)d_in[18];
    const float* ec_w2 = (const float*)d_in[19];
    const float* ec_b2 = (const float*)d_in[20];

    float *gx1, *gx2, *gx3, *gA, *gB, *gsf, *ghi, *ghj, *ghg;
    int* gidx;
    cudaGetSymbolAddress((void**)&gx1, g_x1);
    cudaGetSymbolAddress((void**)&gx2, g_x2);
    cudaGetSymbolAddress((void**)&gx3, g_x3);
    cudaGetSymbolAddress((void**)&gidx, g_idx);
    cudaGetSymbolAddress((void**)&gA,  g_A);
    cudaGetSymbolAddress((void**)&gB,  g_Bv);
    cudaGetSymbolAddress((void**)&gsf, g_sf);
    cudaGetSymbolAddress((void**)&ghi, g_hi);
    cudaGetSymbolAddress((void**)&ghj, g_hj);
    cudaGetSymbolAddress((void**)&ghg, g_hg);

    const int NB = BATCH * NPT;

    // conv1: pos(3) -> x1(32), MLP 6->16->32
    knn_kernel<<<NB, 128>>>(pos, 3, gidx);
    ab_kernel<<<NB, 64>>>(pos, c1_w1, 3, 16, gA, gB);
    edge_kernel<16, 32, 32, 1><<<NB, 32>>>(gA, gB, gidx, c1_b1, c1_w2, c1_b2, gx1);

    // conv2: x1(32) -> x2(128), MLP 64->64->128
    knn_kernel<<<NB, 128>>>(gx1, 32, gidx);
    ab_kernel<<<NB, 64>>>(gx1, c2_w1, 32, 64, gA, gB);
    edge_kernel<64, 128, 128, 1><<<NB, 128>>>(gA, gB, gidx, c2_b1, c2_w2, c2_b2, gx2);

    // conv3: x2(128) -> x3(512), MLP 256->256->512
    knn_kernel<<<NB, 128>>>(gx2, 128, gidx);
    ab_kernel<<<NB, 256>>>(gx2, c3_w1, 128, 256, gA, gB);
    edge_kernel<256, 512, 128, 4><<<NB, 128>>>(gA, gB, gidx, c3_b1, c3_w2, c3_b2, gx3);

    // sf MLP + hi/hj projections
    sf_kernel<<<NB, 256>>>(gx1, gx2, gx3, sm_w1, sm_b1, sm_w2, sm_b2, ec_w1, gsf, ghi, ghj);

    // global max pool + hg
    gmax_kernel<<<BATCH, 128>>>(gsf, ec_w1, ec_b1, ghg);

    // all-pairs
    int writeBoth = (out_size >= 2 * BATCH * NPAIR) ? 1 : 0;
    dim3 grid(32, 32, BATCH);
    pairs_kernel<<<grid, 256>>>(ghi, ghj, ghg, ec_w2, ec_b2, (float*)d_out, writeBoth);
}

// round 2
// speedup vs baseline: 3.0411x; 3.0411x over previous
#include <cuda_runtime.h>
#include <math.h>

#define BATCH 2
#define NPT   1000
#define KNN   8
#define NPAIR 499500   // N*(N-1)/2

// ---------------- static scratch (no allocation allowed) ----------------
__device__ float g_x1[BATCH * NPT * 32];
__device__ float g_x2[BATCH * NPT * 128];
__device__ float g_x3[BATCH * NPT * 512];
__device__ int   g_idx[BATCH * NPT * KNN];
__device__ float g_A [BATCH * NPT * 256];
__device__ float g_Bv[BATCH * NPT * 256];
__device__ float g_sf[BATCH * NPT * 128];
__device__ float g_hi[BATCH * NPT * 128];
__device__ float g_hj[BATCH * NPT * 128];
__device__ float g_hg[BATCH * 128];
__device__ float g_d2[(size_t)BATCH * NPT * NPT];   // ranking value s_j = |xj|^2 - 2<xi,xj>
__device__ float g_sq[BATCH * NPT];

// ---------------- per-node squared norms ----------------
__global__ void sq_kernel(const float* __restrict__ x, int C, float* __restrict__ sq) {
    int node = blockIdx.x * blockDim.x + threadIdx.x;
    if (node >= BATCH * NPT) return;
    float s = 0.f;
    const float* xr = x + (size_t)node * C;
    for (int c = 0; c < C; c++) s = fmaf(xr[c], xr[c], s);
    sq[node] = s;
}

// ---------------- pairwise ranking value: s[i][j] = sq[j] - 2*dot(xi,xj) ----------------
// 64x64 tile per block, 256 threads, 4x4 register block, K-chunks of 16.
__global__ void d2_kernel(const float* __restrict__ x, const float* __restrict__ sq,
                          int C, float* __restrict__ out) {
    int b  = blockIdx.z;
    int i0 = blockIdx.y * 64;
    int j0 = blockIdx.x * 64;
    __shared__ float xaT[16][72];   // [k][row], padded
    __shared__ float xbT[16][72];

    int tid = threadIdx.x;          // 256
    int tx = tid & 15, ty = tid >> 4;

    float dot[4][4];
#pragma unroll
    for (int u = 0; u < 4; u++)
#pragma unroll
        for (int v = 0; v < 4; v++) dot[u][v] = 0.f;

    for (int k0 = 0; k0 < C; k0 += 16) {
        for (int t = tid; t < 2048; t += 256) {
            int half = t >> 10;
            int r  = (t >> 4) & 63;
            int kk = t & 15;
            int cc = k0 + kk;
            int nn = (half ? j0 : i0) + r;
            float v = 0.f;
            if (cc < C && nn < NPT) v = x[((size_t)(b * NPT + nn)) * C + cc];
            if (half) xbT[kk][r] = v; else xaT[kk][r] = v;
        }
        __syncthreads();
#pragma unroll
        for (int kk = 0; kk < 16; kk++) {
            float4 a  = *reinterpret_cast<const float4*>(&xaT[kk][ty * 4]);
            float4 bb = *reinterpret_cast<const float4*>(&xbT[kk][tx * 4]);
            float av[4] = {a.x, a.y, a.z, a.w};
            float bv[4] = {bb.x, bb.y, bb.z, bb.w};
#pragma unroll
            for (int u = 0; u < 4; u++)
#pragma unroll
                for (int v = 0; v < 4; v++)
                    dot[u][v] = fmaf(av[u], bv[v], dot[u][v]);
        }
        __syncthreads();
    }
#pragma unroll
    for (int u = 0; u < 4; u++) {
        int i = i0 + ty * 4 + u;
        if (i >= NPT) continue;
#pragma unroll
        for (int v = 0; v < 4; v++) {
            int j = j0 + tx * 4 + v;
            if (j >= NPT) continue;
            out[(size_t)(b * NPT + i) * NPT + j] = sq[b * NPT + j] - 2.f * dot[u][v];
        }
    }
}

// ---------------- top-8 per row: one warp per row ----------------
__global__ void topk_kernel(const float* __restrict__ d2, int* __restrict__ idxout) {
    int warp = threadIdx.x >> 5, lane = threadIdx.x & 31;
    int node = blockIdx.x * 4 + warp;
    const float* row = d2 + (size_t)node * NPT;

    float bd[8]; int bi[8];
#pragma unroll
    for (int s = 0; s < 8; s++) { bd[s] = 3.4e38f; bi[s] = 0x7fffffff; }

    for (int j = lane; j < NPT; j += 32) {
        float v = row[j];
        if (v < bd[7] || (v == bd[7] && j < bi[7])) {
            int p = 7;
            while (p > 0 && (v < bd[p-1] || (v == bd[p-1] && j < bi[p-1]))) {
                bd[p] = bd[p-1]; bi[p] = bi[p-1]; p--;
            }
            bd[p] = v; bi[p] = j;
        }
    }

    __shared__ float sd[4][32][8];
    __shared__ int   si[4][32][8];
#pragma unroll
    for (int s = 0; s < 8; s++) { sd[warp][lane][s] = bd[s]; si[warp][lane][s] = bi[s]; }
    __syncwarp();

    for (int str = 16; str > 0; str >>= 1) {
        if (lane < str) {
            float* A1 = sd[warp][lane];        int* I1 = si[warp][lane];
            float* A2 = sd[warp][lane + str];  int* I2 = si[warp][lane + str];
            float od[8]; int oi[8];
            int a = 0, c2 = 0;
#pragma unroll
            for (int t = 0; t < 8; t++) {
                bool takeA = (A1[a] < A2[c2]) || (A1[a] == A2[c2] && I1[a] <= I2[c2]);
                if (takeA) { od[t] = A1[a]; oi[t] = I1[a]; a++; }
                else       { od[t] = A2[c2]; oi[t] = I2[c2]; c2++; }
            }
#pragma unroll
            for (int t = 0; t < 8; t++) { A1[t] = od[t]; I1[t] = oi[t]; }
        }
        __syncwarp();
    }
    if (lane < 8) idxout[node * 8 + lane] = si[warp][0][lane];
}

// ---------------- per-node A = x@W1_top, Bv = x@W1_bot (8 nodes/block) ----------------
template<int NPB>
__global__ void ab_kernel(const float* __restrict__ x, const float* __restrict__ w1,
                          int C, int H, float* __restrict__ A, float* __restrict__ Bv) {
    int n0 = blockIdx.x * NPB;
    int tid = threadIdx.x;          // H threads
    __shared__ float xs[NPB][128];
    for (int t = tid; t < NPB * C; t += blockDim.x) {
        int nn = t / C, c = t % C;
        xs[nn][c] = x[(size_t)(n0 + nn) * C + c];
    }
    __syncthreads();
    float a[NPB], bb[NPB];
#pragma unroll
    for (int nn = 0; nn < NPB; nn++) { a[nn] = 0.f; bb[nn] = 0.f; }
    for (int c = 0; c < C; c++) {
        float wt = w1[c * H + tid];
        float wb = w1[(C + c) * H + tid];
#pragma unroll
        for (int nn = 0; nn < NPB; nn++) {
            float v = xs[nn][c];
            a[nn]  = fmaf(v, wt, a[nn]);
            bb[nn] = fmaf(v, wb, bb[nn]);
        }
    }
#pragma unroll
    for (int nn = 0; nn < NPB; nn++) {
        A [(size_t)(n0 + nn) * H + tid] = a[nn];
        Bv[(size_t)(n0 + nn) * H + tid] = bb[nn];
    }
}

// ---------------- edge MLP2 + max aggregation ----------------
// Hoist all 8 neighbor activations into shared first, then ONE pass over w2.
template<int H, int COUT, int T, int VC>
__global__ void edge_kernel(const float* __restrict__ A, const float* __restrict__ Bv,
                            const int* __restrict__ idx, const float* __restrict__ b1,
                            const float* __restrict__ w2, const float* __restrict__ b2,
                            float* __restrict__ xout) {
    static_assert(T * VC == COUT, "layout");
    int node = blockIdx.x;
    int tid = threadIdx.x;
    __shared__ float aic[H];
    __shared__ float hsh[KNN][H];
    __shared__ int   js[KNN];

    if (tid < KNN) js[tid] = idx[node * KNN + tid];
    for (int hh = tid; hh < H; hh += T)
        aic[hh] = A[(size_t)node * H + hh] - Bv[(size_t)node * H + hh] + b1[hh];
    __syncthreads();

    int bbase = (node / NPT) * NPT;
#pragma unroll
    for (int k = 0; k < KNN; k++) {
        const float* bvj = Bv + (size_t)(bbase + js[k]) * H;
        for (int hh = tid; hh < H; hh += T)
            hsh[k][hh] = fmaxf(aic[hh] + bvj[hh], 0.f);
    }
    __syncthreads();

    float acc[KNN][VC];
#pragma unroll
    for (int k = 0; k < KNN; k++)
#pragma unroll
        for (int v = 0; v < VC; v++) acc[k][v] = 0.f;

#pragma unroll 4
    for (int hh = 0; hh < H; hh++) {
        float w[VC];
        if (VC == 4) {
            float4 wv = *reinterpret_cast<const float4*>(w2 + (size_t)hh * COUT + tid * 4);
            w[0] = wv.x; w[1] = wv.y; w[2] = wv.z; w[3] = wv.w;
        } else {
#pragma unroll
            for (int v = 0; v < VC; v++) w[v] = w2[(size_t)hh * COUT + tid * VC + v];
        }
#pragma unroll
        for (int k = 0; k < KNN; k++) {
            float hv = hsh[k][hh];
#pragma unroll
            for (int v = 0; v < VC; v++) acc[k][v] = fmaf(hv, w[v], acc[k][v]);
        }
    }

#pragma unroll
    for (int v = 0; v < VC; v++) {
        float m = -3.4e38f;
#pragma unroll
        for (int k = 0; k < KNN; k++) m = fmaxf(m, acc[k][v]);
        xout[(size_t)node * COUT + tid * VC + v] = m + b2[tid * VC + v];
    }
}

// ---------------- sf = MLP(concat(x1,x2,x3)); also hi/hj projections ----------------
__global__ void sf_kernel(const float* __restrict__ x1, const float* __restrict__ x2,
                          const float* __restrict__ x3,
                          const float* __restrict__ w1, const float* __restrict__ b1,
                          const float* __restrict__ w2, const float* __restrict__ b2,
                          const float* __restrict__ ecw1,
                          float* __restrict__ sf, float* __restrict__ hi, float* __restrict__ hj) {
    int node = blockIdx.x;
    int tid = threadIdx.x;   // 256
    __shared__ float xin[672];
    __shared__ float hsh[256];
    __shared__ float sfs[128];

    for (int c = tid; c < 32;  c += 256) xin[c]       = x1[node * 32 + c];
    for (int c = tid; c < 128; c += 256) xin[32 + c]  = x2[node * 128 + c];
    for (int c = tid; c < 512; c += 256) xin[160 + c] = x3[(size_t)node * 512 + c];
    __syncthreads();

    {
        float acc = b1[tid];
#pragma unroll 4
        for (int d = 0; d < 672; d++) acc = fmaf(xin[d], w1[d * 256 + tid], acc);
        hsh[tid] = fmaxf(acc, 0.f);
    }
    __syncthreads();

    if (tid < 128) {
        float acc = b2[tid];
#pragma unroll 8
        for (int d = 0; d < 256; d++) acc = fmaf(hsh[d], w2[d * 128 + tid], acc);
        sfs[tid] = acc;
        sf[node * 128 + tid] = acc;
    }
    __syncthreads();

    if (tid < 128) {
        float a1 = 0.f, a2 = 0.f;
#pragma unroll 8
        for (int d = 0; d < 128; d++) {
            float s = sfs[d];
            a1 = fmaf(s, ecw1[d * 128 + tid],         a1);
            a2 = fmaf(s, ecw1[(128 + d) * 128 + tid], a2);
        }
        hi[node * 128 + tid] = a1;
        hj[node * 128 + tid] = a2;
    }
}

// ---------------- global max pool + hg = g@ec_w1[256:] + ec_b1 ----------------
__global__ void gmax_kernel(const float* __restrict__ sf, const float* __restrict__ ecw1,
                            const float* __restrict__ ecb1, float* __restrict__ hg) {
    int b = blockIdx.x;
    int tid = threadIdx.x;  // 128
    __shared__ float gsh[128];
    float m = -3.4e38f;
    for (int n = 0; n < NPT; n++)
        m = fmaxf(m, sf[(size_t)(b * NPT + n) * 128 + tid]);
    gsh[tid] = m;
    __syncthreads();
    float acc = ecb1[tid];
#pragma unroll 8
    for (int d = 0; d < 128; d++)
        acc = fmaf(gsh[d], ecw1[(256 + d) * 128 + tid], acc);
    hg[b * 128 + tid] = acc;
}

// ---------------- all-pairs classifier: 32x32 tiles over triu pairs ----------------
__global__ void pairs_kernel(const float* __restrict__ hi, const float* __restrict__ hj,
                             const float* __restrict__ hg, const float* __restrict__ ecw2,
                             const float* __restrict__ ecb2, float* __restrict__ out,
                             int writeBoth) {
    int it = blockIdx.x, jt = blockIdx.y, b = blockIdx.z;
    if (jt < it) return;

    __shared__ float shi[32 * 128];
    __shared__ float shj[32 * 128];
    __shared__ float w2s[128];

    int tid = threadIdx.x;  // 256
    if (tid < 128) w2s[tid] = ecw2[tid];

    for (int t = tid; t < 32 * 128; t += 256) {
        int r = t >> 7, c = t & 127;
        int i = it * 32 + r;
        shi[t] = (i < NPT) ? (hi[(size_t)(b * NPT + i) * 128 + c] + hg[b * 128 + c]) : 0.f;
        int j = jt * 32 + r;
        shj[t] = (j < NPT) ? hj[(size_t)(b * NPT + j) * 128 + c] : 0.f;
    }
    __syncthreads();

    int warp = tid >> 5, lane = tid & 31;
    float w0 = w2s[lane * 4 + 0];
    float w1 = w2s[lane * 4 + 1];
    float w2v = w2s[lane * 4 + 2];
    float w3 = w2s[lane * 4 + 3];
    float bias = ecb2[0];

    const float4* shi4 = reinterpret_cast<const float4*>(shi);
    const float4* shj4 = reinterpret_cast<const float4*>(shj);

    for (int lp = warp; lp < 1024; lp += 8) {
        int ri = lp >> 5, rj = lp & 31;
        int i = it * 32 + ri, j = jt * 32 + rj;
        if (i >= NPT || j >= NPT || j <= i) continue;

        float4 a = shi4[ri * 32 + lane];
        float4 bb = shj4[rj * 32 + lane];
        float acc = fmaxf(a.x + bb.x, 0.f) * w0
                  + fmaxf(a.y + bb.y, 0.f) * w1
                  + fmaxf(a.z + bb.z, 0.f) * w2v
                  + fmaxf(a.w + bb.w, 0.f) * w3;
#pragma unroll
        for (int s = 16; s > 0; s >>= 1) acc += __shfl_down_sync(0xffffffffu, acc, s);

        if (lane == 0) {
            float v = acc + bias;
            int p = i * (NPT - 1) - (i * (i - 1)) / 2 + (j - i - 1);
            float prob = 1.f / (1.f + expf(-v));
            size_t base = (size_t)b * NPAIR + p;
            out[base] = prob;
            if (writeBoth) out[(size_t)BATCH * NPAIR + base] = v;
        }
    }
}

// ---------------- host launch ----------------
static void run_knn(const float* x, int C, float* gd2, float* gsq, int* gidx) {
    sq_kernel<<<(BATCH * NPT + 127) / 128, 128>>>(x, C, gsq);
    dim3 dg(16, 16, BATCH);
    d2_kernel<<<dg, 256>>>(x, gsq, C, gd2);
    topk_kernel<<<(BATCH * NPT) / 4, 128>>>(gd2, gidx);
}

extern "C" void kernel_launch(void* const* d_in, const int* in_sizes, int n_in,
                              void* d_out, int out_size) {
    const float* pos   = (const float*)d_in[0];
    const float* c1_w1 = (const float*)d_in[1];
    const float* c1_b1 = (const float*)d_in[2];
    const float* c1_w2 = (const float*)d_in[3];
    const float* c1_b2 = (const float*)d_in[4];
    const float* c2_w1 = (const float*)d_in[5];
    const float* c2_b1 = (const float*)d_in[6];
    const float* c2_w2 = (const float*)d_in[7];
    const float* c2_b2 = (const float*)d_in[8];
    const float* c3_w1 = (const float*)d_in[9];
    const float* c3_b1 = (const float*)d_in[10];
    const float* c3_w2 = (const float*)d_in[11];
    const float* c3_b2 = (const float*)d_in[12];
    const float* sm_w1 = (const float*)d_in[13];
    const float* sm_b1 = (const float*)d_in[14];
    const float* sm_w2 = (const float*)d_in[15];
    const float* sm_b2 = (const float*)d_in[16];
    const float* ec_w1 = (const float*)d_in[17];
    const float* ec_b1 = (const float*)d_in[18];
    const float* ec_w2 = (const float*)d_in[19];
    const float* ec_b2 = (const float*)d_in[20];

    float *gx1, *gx2, *gx3, *gA, *gB, *gsf, *ghi, *ghj, *ghg, *gd2, *gsq;
    int* gidx;
    cudaGetSymbolAddress((void**)&gx1, g_x1);
    cudaGetSymbolAddress((void**)&gx2, g_x2);
    cudaGetSymbolAddress((void**)&gx3, g_x3);
    cudaGetSymbolAddress((void**)&gidx, g_idx);
    cudaGetSymbolAddress((void**)&gA,  g_A);
    cudaGetSymbolAddress((void**)&gB,  g_Bv);
    cudaGetSymbolAddress((void**)&gsf, g_sf);
    cudaGetSymbolAddress((void**)&ghi, g_hi);
    cudaGetSymbolAddress((void**)&ghj, g_hj);
    cudaGetSymbolAddress((void**)&ghg, g_hg);
    cudaGetSymbolAddress((void**)&gd2, g_d2);
    cudaGetSymbolAddress((void**)&gsq, g_sq);

    const int NB = BATCH * NPT;

    // conv1: pos(3) -> x1(32), MLP 6->16->32
    run_knn(pos, 3, gd2, gsq, gidx);
    ab_kernel<8><<<NB / 8, 16>>>(pos, c1_w1, 3, 16, gA, gB);
    edge_kernel<16, 32, 32, 1><<<NB, 32>>>(gA, gB, gidx, c1_b1, c1_w2, c1_b2, gx1);

    // conv2: x1(32) -> x2(128), MLP 64->64->128
    run_knn(gx1, 32, gd2, gsq, gidx);
    ab_kernel<8><<<NB / 8, 64>>>(gx1, c2_w1, 32, 64, gA, gB);
    edge_kernel<64, 128, 128, 1><<<NB, 128>>>(gA, gB, gidx, c2_b1, c2_w2, c2_b2, gx2);

    // conv3: x2(128) -> x3(512), MLP 256->256->512
    run_knn(gx2, 128, gd2, gsq, gidx);
    ab_kernel<8><<<NB / 8, 256>>>(gx2, c3_w1, 128, 256, gA, gB);
    edge_kernel<256, 512, 128, 4><<<NB, 128>>>(gA, gB, gidx, c3_b1, c3_w2, c3_b2, gx3);

    // sf MLP + hi/hj projections
    sf_kernel<<<NB, 256>>>(gx1, gx2, gx3, sm_w1, sm_b1, sm_w2, sm_b2, ec_w1, gsf, ghi, ghj);

    // global max pool + hg
    gmax_kernel<<<BATCH, 128>>>(gsf, ec_w1, ec_b1, ghg);

    // all-pairs
    int writeBoth = (out_size >= 2 * BATCH * NPAIR) ? 1 : 0;
    dim3 grid(32, 32, BATCH);
    pairs_kernel<<<grid, 256>>>(ghi, ghj, ghg, ec_w2, ec_b2, (float*)d_out, writeBoth);
}

// round 3
// speedup vs baseline: 3.0537x; 1.0041x over previous
#include <cuda_runtime.h>
#include <math.h>

#define BATCH 2
#define NPT   1000
#define KNN   8
#define NPAIR 499500   // N*(N-1)/2

// ---------------- static scratch (no allocation allowed) ----------------
__device__ float g_x1[BATCH * NPT * 32];
__device__ float g_x2[BATCH * NPT * 128];
__device__ float g_x3[BATCH * NPT * 512];
__device__ int   g_idx[BATCH * NPT * KNN];
__device__ float g_A [BATCH * NPT * 256];
__device__ float g_Bv[BATCH * NPT * 256];
__device__ float g_sf[BATCH * NPT * 128];
__device__ float g_hi[BATCH * NPT * 128];
__device__ float g_hj[BATCH * NPT * 128];
__device__ float g_hg[BATCH * 128];
__device__ float g_d2[(size_t)BATCH * NPT * NPT];
__device__ float g_sq[BATCH * NPT];

// ---------------- per-node squared norms ----------------
__global__ void sq_kernel(const float* __restrict__ x, int C, float* __restrict__ sq) {
    int node = blockIdx.x * blockDim.x + threadIdx.x;
    if (node >= BATCH * NPT) return;
    float s = 0.f;
    const float* xr = x + (size_t)node * C;
    for (int c = 0; c < C; c++) s = fmaf(xr[c], xr[c], s);
    sq[node] = s;
}

// ---------------- pairwise ranking value: s[i][j] = sq[j] - 2*dot(xi,xj) ----------------
__global__ void d2_kernel(const float* __restrict__ x, const float* __restrict__ sq,
                          int C, float* __restrict__ out) {
    int b  = blockIdx.z;
    int i0 = blockIdx.y * 64;
    int j0 = blockIdx.x * 64;
    __shared__ float xaT[16][72];
    __shared__ float xbT[16][72];

    int tid = threadIdx.x;          // 256
    int tx = tid & 15, ty = tid >> 4;

    float dot[4][4];
#pragma unroll
    for (int u = 0; u < 4; u++)
#pragma unroll
        for (int v = 0; v < 4; v++) dot[u][v] = 0.f;

    for (int k0 = 0; k0 < C; k0 += 16) {
        for (int t = tid; t < 2048; t += 256) {
            int half = t >> 10;
            int r  = (t >> 4) & 63;
            int kk = t & 15;
            int cc = k0 + kk;
            int nn = (half ? j0 : i0) + r;
            float v = 0.f;
            if (cc < C && nn < NPT) v = x[((size_t)(b * NPT + nn)) * C + cc];
            if (half) xbT[kk][r] = v; else xaT[kk][r] = v;
        }
        __syncthreads();
#pragma unroll
        for (int kk = 0; kk < 16; kk++) {
            float4 a  = *reinterpret_cast<const float4*>(&xaT[kk][ty * 4]);
            float4 bb = *reinterpret_cast<const float4*>(&xbT[kk][tx * 4]);
            float av[4] = {a.x, a.y, a.z, a.w};
            float bv[4] = {bb.x, bb.y, bb.z, bb.w};
#pragma unroll
            for (int u = 0; u < 4; u++)
#pragma unroll
                for (int v = 0; v < 4; v++)
                    dot[u][v] = fmaf(av[u], bv[v], dot[u][v]);
        }
        __syncthreads();
    }
#pragma unroll
    for (int u = 0; u < 4; u++) {
        int i = i0 + ty * 4 + u;
        if (i >= NPT) continue;
#pragma unroll
        for (int v = 0; v < 4; v++) {
            int j = j0 + tx * 4 + v;
            if (j >= NPT) continue;
            out[(size_t)(b * NPT + i) * NPT + j] = sq[b * NPT + j] - 2.f * dot[u][v];
        }
    }
}

// ---------------- top-8 per row: one warp per row ----------------
__global__ void topk_kernel(const float* __restrict__ d2, int* __restrict__ idxout) {
    int warp = threadIdx.x >> 5, lane = threadIdx.x & 31;
    int node = blockIdx.x * 4 + warp;
    const float* row = d2 + (size_t)node * NPT;

    float bd[8]; int bi[8];
#pragma unroll
    for (int s = 0; s < 8; s++) { bd[s] = 3.4e38f; bi[s] = 0x7fffffff; }

    for (int j = lane; j < NPT; j += 32) {
        float v = row[j];
        if (v < bd[7] || (v == bd[7] && j < bi[7])) {
            int p = 7;
            while (p > 0 && (v < bd[p-1] || (v == bd[p-1] && j < bi[p-1]))) {
                bd[p] = bd[p-1]; bi[p] = bi[p-1]; p--;
            }
            bd[p] = v; bi[p] = j;
        }
    }

    __shared__ float sd[4][32][8];
    __shared__ int   si[4][32][8];
#pragma unroll
    for (int s = 0; s < 8; s++) { sd[warp][lane][s] = bd[s]; si[warp][lane][s] = bi[s]; }
    __syncwarp();

    for (int str = 16; str > 0; str >>= 1) {
        if (lane < str) {
            float* A1 = sd[warp][lane];        int* I1 = si[warp][lane];
            float* A2 = sd[warp][lane + str];  int* I2 = si[warp][lane + str];
            float od[8]; int oi[8];
            int a = 0, c2 = 0;
#pragma unroll
            for (int t = 0; t < 8; t++) {
                bool takeA = (A1[a] < A2[c2]) || (A1[a] == A2[c2] && I1[a] <= I2[c2]);
                if (takeA) { od[t] = A1[a]; oi[t] = I1[a]; a++; }
                else       { od[t] = A2[c2]; oi[t] = I2[c2]; c2++; }
            }
#pragma unroll
            for (int t = 0; t < 8; t++) { A1[t] = od[t]; I1[t] = oi[t]; }
        }
        __syncwarp();
    }
    if (lane < 8) idxout[node * 8 + lane] = si[warp][0][lane];
}

// ---------------- per-node A = x@W1_top, Bv = x@W1_bot (8 nodes/block) ----------------
template<int NPB>
__global__ void ab_kernel(const float* __restrict__ x, const float* __restrict__ w1,
                          int C, int H, float* __restrict__ A, float* __restrict__ Bv) {
    int n0 = blockIdx.x * NPB;
    int tid = threadIdx.x;          // H threads
    __shared__ float xs[NPB][128];
    for (int t = tid; t < NPB * C; t += blockDim.x) {
        int nn = t / C, c = t % C;
        xs[nn][c] = x[(size_t)(n0 + nn) * C + c];
    }
    __syncthreads();
    float a[NPB], bb[NPB];
#pragma unroll
    for (int nn = 0; nn < NPB; nn++) { a[nn] = 0.f; bb[nn] = 0.f; }
    for (int c = 0; c < C; c++) {
        float wt = w1[c * H + tid];
        float wb = w1[(C + c) * H + tid];
#pragma unroll
        for (int nn = 0; nn < NPB; nn++) {
            float v = xs[nn][c];
            a[nn]  = fmaf(v, wt, a[nn]);
            bb[nn] = fmaf(v, wb, bb[nn]);
        }
    }
#pragma unroll
    for (int nn = 0; nn < NPB; nn++) {
        A [(size_t)(n0 + nn) * H + tid] = a[nn];
        Bv[(size_t)(n0 + nn) * H + tid] = bb[nn];
    }
}

// ---------------- edge MLP2 + max aggregation, NPB nodes per block ----------------
// h_{n,k} = relu(A_n - Bv_n + b1 + Bv_{j(n,k)}); out_n = max_k(h_{n,k} @ w2) + b2
template<int H, int COUT, int T, int VC, int NPB>
__global__ void edge_kernel(const float* __restrict__ A, const float* __restrict__ Bv,
                            const int* __restrict__ idx, const float* __restrict__ b1,
                            const float* __restrict__ w2, const float* __restrict__ b2,
                            float* __restrict__ xout) {
    static_assert(T * VC == COUT, "layout");
    int n0 = blockIdx.x * NPB;
    int tid = threadIdx.x;
    __shared__ float aic[NPB][H];
    __shared__ float hsh[NPB][KNN][H];
    __shared__ int   js[NPB][KNN];

    for (int t = tid; t < NPB * KNN; t += T)
        js[t / KNN][t % KNN] = idx[(size_t)(n0 + t / KNN) * KNN + t % KNN];
#pragma unroll
    for (int n = 0; n < NPB; n++)
        for (int hh = tid; hh < H; hh += T)
            aic[n][hh] = A[(size_t)(n0 + n) * H + hh] - Bv[(size_t)(n0 + n) * H + hh] + b1[hh];
    __syncthreads();

    int bbase = (n0 / NPT) * NPT;
#pragma unroll
    for (int n = 0; n < NPB; n++)
#pragma unroll
        for (int k = 0; k < KNN; k++) {
            const float* bvj = Bv + (size_t)(bbase + js[n][k]) * H;
            for (int hh = tid; hh < H; hh += T)
                hsh[n][k][hh] = fmaxf(aic[n][hh] + bvj[hh], 0.f);
        }
    __syncthreads();

    float acc[NPB][KNN][VC];
#pragma unroll
    for (int n = 0; n < NPB; n++)
#pragma unroll
        for (int k = 0; k < KNN; k++)
#pragma unroll
            for (int v = 0; v < VC; v++) acc[n][k][v] = 0.f;

#pragma unroll 2
    for (int hh = 0; hh < H; hh++) {
        float w[VC];
        if (VC == 4) {
            float4 wv = *reinterpret_cast<const float4*>(w2 + (size_t)hh * COUT + tid * 4);
            w[0] = wv.x; w[1] = wv.y; w[2] = wv.z; w[3] = wv.w;
        } else if (VC == 2) {
            float2 wv = *reinterpret_cast<const float2*>(w2 + (size_t)hh * COUT + tid * 2);
            w[0] = wv.x; w[1] = wv.y;
        } else {
            w[0] = w2[(size_t)hh * COUT + tid];
        }
#pragma unroll
        for (int n = 0; n < NPB; n++)
#pragma unroll
            for (int k = 0; k < KNN; k++) {
                float hv = hsh[n][k][hh];
#pragma unroll
                for (int v = 0; v < VC; v++) acc[n][k][v] = fmaf(hv, w[v], acc[n][k][v]);
            }
    }

#pragma unroll
    for (int n = 0; n < NPB; n++)
#pragma unroll
        for (int v = 0; v < VC; v++) {
            float m = -3.4e38f;
#pragma unroll
            for (int k = 0; k < KNN; k++) m = fmaxf(m, acc[n][k][v]);
            xout[(size_t)(n0 + n) * COUT + tid * VC + v] = m + b2[tid * VC + v];
        }
}

// ---------------- sf = MLP(concat(x1,x2,x3)); also hi/hj projections ----------------
// NPB=8 nodes per block, 256 threads.
#define SF_NPB 8
__global__ void sf_kernel(const float* __restrict__ x1, const float* __restrict__ x2,
                          const float* __restrict__ x3,
                          const float* __restrict__ w1, const float* __restrict__ b1,
                          const float* __restrict__ w2, const float* __restrict__ b2,
                          const float* __restrict__ ecw1,
                          float* __restrict__ sf, float* __restrict__ hi, float* __restrict__ hj) {
    int n0 = blockIdx.x * SF_NPB;
    int tid = threadIdx.x;   // 256
    __shared__ float xin[SF_NPB][672];
    __shared__ float hsh[SF_NPB][256];
    __shared__ float sfs[SF_NPB][128];

    for (int t = tid; t < SF_NPB * 32; t += 256)
        xin[t >> 5][t & 31] = x1[(size_t)(n0 + (t >> 5)) * 32 + (t & 31)];
    for (int t = tid; t < SF_NPB * 128; t += 256)
        xin[t >> 7][32 + (t & 127)] = x2[(size_t)(n0 + (t >> 7)) * 128 + (t & 127)];
    for (int t = tid; t < SF_NPB * 512; t += 256)
        xin[t >> 9][160 + (t & 511)] = x3[(size_t)(n0 + (t >> 9)) * 512 + (t & 511)];
    __syncthreads();

    // layer 1: 672 -> 256 (relu)
    {
        float acc[SF_NPB];
#pragma unroll
        for (int n = 0; n < SF_NPB; n++) acc[n] = b1[tid];
#pragma unroll 2
        for (int d = 0; d < 672; d++) {
            float wv = w1[d * 256 + tid];
#pragma unroll
            for (int n = 0; n < SF_NPB; n++) acc[n] = fmaf(xin[n][d], wv, acc[n]);
        }
#pragma unroll
        for (int n = 0; n < SF_NPB; n++) hsh[n][tid] = fmaxf(acc[n], 0.f);
    }
    __syncthreads();

    // layer 2: 256 -> 128.  threads split: grp = tid>>7 handles nodes grp*4..grp*4+3
    int col = tid & 127;
    int gn = (tid >> 7) * (SF_NPB / 2);
    {
        float acc[SF_NPB / 2];
#pragma unroll
        for (int n = 0; n < SF_NPB / 2; n++) acc[n] = b2[col];
#pragma unroll 4
        for (int d = 0; d < 256; d++) {
            float wv = w2[d * 128 + col];
#pragma unroll
            for (int n = 0; n < SF_NPB / 2; n++) acc[n] = fmaf(hsh[gn + n][d], wv, acc[n]);
        }
#pragma unroll
        for (int n = 0; n < SF_NPB / 2; n++) {
            sfs[gn + n][col] = acc[n];
            sf[(size_t)(n0 + gn + n) * 128 + col] = acc[n];
        }
    }
    __syncthreads();

    // hi/hj projections: sfs @ ecw1[:128] and sfs @ ecw1[128:256]
    {
        float a1[SF_NPB / 2], a2[SF_NPB / 2];
#pragma unroll
        for (int n = 0; n < SF_NPB / 2; n++) { a1[n] = 0.f; a2[n] = 0.f; }
#pragma unroll 4
        for (int d = 0; d < 128; d++) {
            float wt = ecw1[d * 128 + col];
            float wb = ecw1[(128 + d) * 128 + col];
#pragma unroll
            for (int n = 0; n < SF_NPB / 2; n++) {
                float s = sfs[gn + n][d];
                a1[n] = fmaf(s, wt, a1[n]);
                a2[n] = fmaf(s, wb, a2[n]);
            }
        }
#pragma unroll
        for (int n = 0; n < SF_NPB / 2; n++) {
            hi[(size_t)(n0 + gn + n) * 128 + col] = a1[n];
            hj[(size_t)(n0 + gn + n) * 128 + col] = a2[n];
        }
    }
}

// ---------------- global max pool + hg = g@ec_w1[256:] + ec_b1 ----------------
__global__ void gmax_kernel(const float* __restrict__ sf, const float* __restrict__ ecw1,
                            const float* __restrict__ ecb1, float* __restrict__ hg) {
    int b = blockIdx.x;
    int tid = threadIdx.x;  // 128
    __shared__ float gsh[128];
    float m = -3.4e38f;
    for (int n = 0; n < NPT; n++)
        m = fmaxf(m, sf[(size_t)(b * NPT + n) * 128 + tid]);
    gsh[tid] = m;
    __syncthreads();
    float acc = ecb1[tid];
#pragma unroll 8
    for (int d = 0; d < 128; d++)
        acc = fmaf(gsh[d], ecw1[(256 + d) * 128 + tid], acc);
    hg[b * 128 + tid] = acc;
}

// ---------------- all-pairs classifier: 32x32 tiles over triu pairs ----------------
__global__ void pairs_kernel(const float* __restrict__ hi, const float* __restrict__ hj,
                             const float* __restrict__ hg, const float* __restrict__ ecw2,
                             const float* __restrict__ ecb2, float* __restrict__ out,
                             int writeBoth) {
    int it = blockIdx.x, jt = blockIdx.y, b = blockIdx.z;
    if (jt < it) return;

    __shared__ float shi[32 * 128];
    __shared__ float shj[32 * 128];
    __shared__ float w2s[128];

    int tid = threadIdx.x;  // 256
    if (tid < 128) w2s[tid] = ecw2[tid];

    for (int t = tid; t < 32 * 128; t += 256) {
        int r = t >> 7, c = t & 127;
        int i = it * 32 + r;
        shi[t] = (i < NPT) ? (hi[(size_t)(b * NPT + i) * 128 + c] + hg[b * 128 + c]) : 0.f;
        int j = jt * 32 + r;
        shj[t] = (j < NPT) ? hj[(size_t)(b * NPT + j) * 128 + c] : 0.f;
    }
    __syncthreads();

    int warp = tid >> 5, lane = tid & 31;
    float w0 = w2s[lane * 4 + 0];
    float w1 = w2s[lane * 4 + 1];
    float w2v = w2s[lane * 4 + 2];
    float w3 = w2s[lane * 4 + 3];
    float bias = ecb2[0];

    const float4* shi4 = reinterpret_cast<const float4*>(shi);
    const float4* shj4 = reinterpret_cast<const float4*>(shj);

    for (int lp = warp; lp < 1024; lp += 8) {
        int ri = lp >> 5, rj = lp & 31;
        int i = it * 32 + ri, j = jt * 32 + rj;
        if (i >= NPT || j >= NPT || j <= i) continue;

        float4 a = shi4[ri * 32 + lane];
        float4 bb = shj4[rj * 32 + lane];
        float acc = fmaxf(a.x + bb.x, 0.f) * w0
                  + fmaxf(a.y + bb.y, 0.f) * w1
                  + fmaxf(a.z + bb.z, 0.f) * w2v
                  + fmaxf(a.w + bb.w, 0.f) * w3;
#pragma unroll
        for (int s = 16; s > 0; s >>= 1) acc += __shfl_down_sync(0xffffffffu, acc, s);

        if (lane == 0) {
            float v = acc + bias;
            int p = i * (NPT - 1) - (i * (i - 1)) / 2 + (j - i - 1);
            float prob = 1.f / (1.f + expf(-v));
            size_t base = (size_t)b * NPAIR + p;
            out[base] = prob;
            if (writeBoth) out[(size_t)BATCH * NPAIR + base] = v;
        }
    }
}

// ---------------- host launch ----------------
static void run_knn(const float* x, int C, float* gd2, float* gsq, int* gidx) {
    sq_kernel<<<(BATCH * NPT + 127) / 128, 128>>>(x, C, gsq);
    dim3 dg(16, 16, BATCH);
    d2_kernel<<<dg, 256>>>(x, gsq, C, gd2);
    topk_kernel<<<(BATCH * NPT) / 4, 128>>>(gd2, gidx);
}

extern "C" void kernel_launch(void* const* d_in, const int* in_sizes, int n_in,
                              void* d_out, int out_size) {
    const float* pos   = (const float*)d_in[0];
    const float* c1_w1 = (const float*)d_in[1];
    const float* c1_b1 = (const float*)d_in[2];
    const float* c1_w2 = (const float*)d_in[3];
    const float* c1_b2 = (const float*)d_in[4];
    const float* c2_w1 = (const float*)d_in[5];
    const float* c2_b1 = (const float*)d_in[6];
    const float* c2_w2 = (const float*)d_in[7];
    const float* c2_b2 = (const float*)d_in[8];
    const float* c3_w1 = (const float*)d_in[9];
    const float* c3_b1 = (const float*)d_in[10];
    const float* c3_w2 = (const float*)d_in[11];
    const float* c3_b2 = (const float*)d_in[12];
    const float* sm_w1 = (const float*)d_in[13];
    const float* sm_b1 = (const float*)d_in[14];
    const float* sm_w2 = (const float*)d_in[15];
    const float* sm_b2 = (const float*)d_in[16];
    const float* ec_w1 = (const float*)d_in[17];
    const float* ec_b1 = (const float*)d_in[18];
    const float* ec_w2 = (const float*)d_in[19];
    const float* ec_b2 = (const float*)d_in[20];

    float *gx1, *gx2, *gx3, *gA, *gB, *gsf, *ghi, *ghj, *ghg, *gd2, *gsq;
    int* gidx;
    cudaGetSymbolAddress((void**)&gx1, g_x1);
    cudaGetSymbolAddress((void**)&gx2, g_x2);
    cudaGetSymbolAddress((void**)&gx3, g_x3);
    cudaGetSymbolAddress((void**)&gidx, g_idx);
    cudaGetSymbolAddress((void**)&gA,  g_A);
    cudaGetSymbolAddress((void**)&gB,  g_Bv);
    cudaGetSymbolAddress((void**)&gsf, g_sf);
    cudaGetSymbolAddress((void**)&ghi, g_hi);
    cudaGetSymbolAddress((void**)&ghj, g_hj);
    cudaGetSymbolAddress((void**)&ghg, g_hg);
    cudaGetSymbolAddress((void**)&gd2, g_d2);
    cudaGetSymbolAddress((void**)&gsq, g_sq);

    const int NB = BATCH * NPT;

    // conv1: pos(3) -> x1(32), MLP 6->16->32
    run_knn(pos, 3, gd2, gsq, gidx);
    ab_kernel<8><<<NB / 8, 16>>>(pos, c1_w1, 3, 16, gA, gB);
    edge_kernel<16, 32, 32, 1, 4><<<NB / 4, 32>>>(gA, gB, gidx, c1_b1, c1_w2, c1_b2, gx1);

    // conv2: x1(32) -> x2(128), MLP 64->64->128
    run_knn(gx1, 32, gd2, gsq, gidx);
    ab_kernel<8><<<NB / 8, 64>>>(gx1, c2_w1, 32, 64, gA, gB);
    edge_kernel<64, 128, 128, 1, 4><<<NB / 4, 128>>>(gA, gB, gidx, c2_b1, c2_w2, c2_b2, gx2);

    // conv3: x2(128) -> x3(512), MLP 256->256->512
    run_knn(gx2, 128, gd2, gsq, gidx);
    ab_kernel<8><<<NB / 8, 256>>>(gx2, c3_w1, 128, 256, gA, gB);
    edge_kernel<256, 512, 256, 2, 4><<<NB / 4, 256>>>(gA, gB, gidx, c3_b1, c3_w2, c3_b2, gx3);

    // sf MLP + hi/hj projections (8 nodes per block)
    sf_kernel<<<NB / SF_NPB, 256>>>(gx1, gx2, gx3, sm_w1, sm_b1, sm_w2, sm_b2, ec_w1, gsf, ghi, ghj);

    // global max pool + hg
    gmax_kernel<<<BATCH, 128>>>(gsf, ec_w1, ec_b1, ghg);

    // all-pairs
    int writeBoth = (out_size >= 2 * BATCH * NPAIR) ? 1 : 0;
    dim3 grid(32, 32, BATCH);
    pairs_kernel<<<grid, 256>>>(ghi, ghj, ghg, ec_w2, ec_b2, (float*)d_out, writeBoth);
}